// round 1
// baseline (speedup 1.0000x reference)
#include <cuda_runtime.h>
#include <cuda_bf16.h>

// CorrectedHistogramLoss: triangular soft-histogram (R=64) of clip(sim) and
// clip(dissim1), cumsum + dots -> scalar. dissim2/margin/anchor_swap unused.
//
// Strategy: packed-u64 fixed-point shared atomics. Each value contributes
// (1-w) to bin f and w to bin f+1 (adjacent). Quantize both to u32 (scale 2^21),
// pack into one u64, single 64-bit shared atomicAdd into an even-pair or
// odd-pair privatized per-warp copy. Halves atomic count vs float atomics and
// is order-independent (deterministic).

#define NBLK 304      // 2 perfect waves on 152 SMs
#define NTHR 256
#define NWARP (NTHR / 32)
#define RBINS 64
#define FSCALE 2097152.0f   // 2^21

// per-block partial histograms: [block][hist*64 + bin], fully overwritten each run
__device__ float g_part[NBLK][2 * RBINS];

__device__ __forceinline__ void acc_val(unsigned long long* h, float x) {
    float xc = fminf(fmaxf(x, -1.0f), 1.0f);
    float u  = (xc + 1.0f) * 31.5f;      // (x+1)/LAM, LAM = 2/63
    float fl = floorf(u);
    float w  = u - fl;
    int   f  = (int)fl;
    if (w > 0.0f && f < 63) {            // w==0 contributes nothing (matches strict ineq.)
        unsigned int wa = __float2uint_rn((1.0f - w) * FSCALE);  // bin f
        unsigned int wb = __float2uint_rn(w * FSCALE);           // bin f+1
        unsigned long long pk = (unsigned long long)wa | ((unsigned long long)wb << 32);
        // slots 0..31: even-pair copy (bins 2k low, 2k+1 high)
        // slots 32..63: odd-pair copy (bins 2k+1 low, 2k+2 high)
        int slot = (f & 1) ? (32 + ((f - 1) >> 1)) : (f >> 1);
        atomicAdd(h + slot, pk);
    }
}

__global__ void __launch_bounds__(NTHR)
hist_kernel(const float* __restrict__ sim, const float* __restrict__ dis, int n) {
    __shared__ unsigned long long sh[NWARP][2][64];   // [warp][hist][slot], 8KB

    int tid = threadIdx.x;
    int wp  = tid >> 5;

    for (int i = tid; i < NWARP * 2 * 64; i += NTHR)
        ((unsigned long long*)sh)[i] = 0ULL;
    __syncthreads();

    unsigned long long* h0 = sh[wp][0];
    unsigned long long* h1 = sh[wp][1];

    int nv = n >> 2;
    int stride = gridDim.x * blockDim.x;
    const float4* s4 = (const float4*)sim;
    const float4* d4 = (const float4*)dis;

    for (int i = blockIdx.x * blockDim.x + tid; i < nv; i += stride) {
        float4 a = s4[i];
        float4 b = d4[i];
        acc_val(h0, a.x); acc_val(h0, a.y); acc_val(h0, a.z); acc_val(h0, a.w);
        acc_val(h1, b.x); acc_val(h1, b.y); acc_val(h1, b.z); acc_val(h1, b.w);
    }
    // scalar tail (n not multiple of 4)
    if (blockIdx.x == 0 && tid == 0) {
        for (int i = nv << 2; i < n; i++) { acc_val(h0, sim[i]); acc_val(h1, dis[i]); }
    }
    __syncthreads();

    // decode + reduce warps -> per-block partial (128 floats)
    if (tid < 2 * RBINS) {
        int h = tid >> 6;
        int r = tid & 63;
        unsigned long long sum = 0ULL;
        #pragma unroll
        for (int w = 0; w < NWARP; w++) {
            unsigned long long e = sh[w][h][r >> 1];                 // even-pair copy
            sum += (r & 1) ? (e >> 32) : (e & 0xffffffffULL);
            if (r >= 1 && r <= 62) {                                  // odd-pair copy
                int k = (r & 1) ? ((r - 1) >> 1) : ((r >> 1) - 1);
                unsigned long long o = sh[w][h][32 + k];
                sum += (r & 1) ? (o & 0xffffffffULL) : (o >> 32);
            }
        }
        g_part[blockIdx.x][tid] = (float)sum;
    }
}

__global__ void __launch_bounds__(1024)
final_kernel(float* __restrict__ out, int n) {
    __shared__ float red[8][2 * RBINS];
    __shared__ float hist[2 * RBINS];

    int tid = threadIdx.x;
    int bin = tid & 127;
    int j   = tid >> 7;          // 0..7

    float s = 0.0f;
    for (int b = j; b < NBLK; b += 8) s += g_part[b][bin];   // warp reads are coalesced
    red[j][bin] = s;
    __syncthreads();

    if (tid < 2 * RBINS) {
        float t = 0.0f;
        #pragma unroll
        for (int k = 0; k < 8; k++) t += red[k][tid];
        hist[tid] = t / ((float)n * FSCALE);
    }
    __syncthreads();

    if (tid == 0) {
        const float q = 0.9f, Pp = 0.1f;
        float hp_cum = 0.0f, hm_cum = 0.0f;
        float d1 = 0.0f, d2 = 0.0f, d3 = 0.0f, d4 = 0.0f;
        #pragma unroll
        for (int r = 0; r < RBINS; r++) {
            float hp = hist[r];
            float hm = hist[RBINS + r];
            hp_cum += hp;
            hm_cum += hm;
            d1 += hp_cum * hm;   // hp_cum . hist_minus
            d2 += hp_cum * hp;   // hp_cum . hist_plus
            d3 += hm_cum * hm;   // hm_cum . hist_minus
            d4 += hm_cum * hp;   // hm_cum . hist_plus
        }
        float num = q * q * d1 - q * Pp * d2 - q * Pp * d3 + Pp * Pp * d4;
        out[0] = num / (1.0f - 4.0f * Pp + 4.0f * Pp * Pp);   // /0.64
    }
}

extern "C" void kernel_launch(void* const* d_in, const int* in_sizes, int n_in,
                              void* d_out, int out_size) {
    const float* sim = (const float*)d_in[0];
    const float* dis = (const float*)d_in[1];   // dissim1; dissim2/margin/anchor_swap unused
    int n = in_sizes[0];

    hist_kernel<<<NBLK, NTHR>>>(sim, dis, n);
    final_kernel<<<1, 1024>>>((float*)d_out, n);
}